// round 1
// baseline (speedup 1.0000x reference)
#include <cuda_runtime.h>
#include <cstdint>
#include <cstddef>

#define BATCH 64
#define SEQ   512
#define HID   300
#define UN    512
#define G3    1536
#define NCTA  128

// ---------------- scratch (device globals: allocation-free rule) ----------------
static __device__ float g_xg[(size_t)SEQ * G3 * BATCH];   // [s][k3][b]  (201 MB)
static __device__ float g_y0[(size_t)SEQ * BATCH * UN];   // [s][b][u]   (67 MB)
static __device__ float g_h[2][UN][BATCH];                // double-buffered h, [unit][batch]
static __device__ unsigned g_count;
static __device__ unsigned g_gen;

__device__ __forceinline__ float sigf(float x) { return 1.f / (1.f + __expf(-x)); }

// Two-variable grid barrier. Called by thread 0 of each CTA only.
// g_gen is monotonically increasing across launches/replays; comparisons are
// relative to the value sampled at kernel start (wrap-safe unsigned compare).
__device__ __forceinline__ void grid_bar_impl(unsigned target, unsigned base) {
    __threadfence();
    unsigned old = atomicAdd(&g_count, 1u);
    if (old == NCTA - 1u) {
        g_count = 0u;
        __threadfence();
        atomicAdd(&g_gen, 1u);
    } else {
        while ((unsigned)(*(volatile unsigned*)&g_gen - base) < target) {}
    }
    __threadfence();
}

// ---------------- layer-0 input projection: xg0[s][k][b] = emb[tok[b,s]] @ W0 + b0[0] ----
// grid (12 ktiles, 512 s), 256 threads, tile 128k x 64b, K=300 in 15 chunks of 20.
__global__ void __launch_bounds__(256) proj0_kernel(const int* __restrict__ tokens,
                                                    const float* __restrict__ emb,
                                                    const float* __restrict__ W0,
                                                    const float* __restrict__ b0) {
    __shared__ float Ws[20][128];
    __shared__ float Es[20][65];
    __shared__ int toks[BATCH];

    const int t  = threadIdx.x;
    const int s  = blockIdx.y;
    const int k0 = blockIdx.x * 128;
    if (t < BATCH) toks[t] = tokens[t * SEQ + s];
    __syncthreads();

    const int tk = t & 15;   // k-subtile (x8)
    const int tb = t >> 4;   // b-subtile (x4)
    float acc[8][4];
#pragma unroll
    for (int i = 0; i < 8; ++i)
#pragma unroll
        for (int j = 0; j < 4; ++j) acc[i][j] = 0.f;

    for (int it = 0; it < 15; ++it) {
        const int d0 = it * 20;
        for (int idx = t; idx < 20 * 128; idx += 256) {
            int r = idx >> 7, c = idx & 127;
            Ws[r][c] = W0[(size_t)(d0 + r) * G3 + k0 + c];
        }
        for (int idx = t; idx < 20 * BATCH; idx += 256) {
            int b = idx / 20, d = idx % 20;
            Es[d][b] = emb[(size_t)toks[b] * HID + d0 + d];
        }
        __syncthreads();
#pragma unroll
        for (int d = 0; d < 20; ++d) {
            float wr[8], er[4];
#pragma unroll
            for (int i = 0; i < 8; ++i) wr[i] = Ws[d][tk * 8 + i];
#pragma unroll
            for (int j = 0; j < 4; ++j) er[j] = Es[d][tb * 4 + j];
#pragma unroll
            for (int i = 0; i < 8; ++i)
#pragma unroll
                for (int j = 0; j < 4; ++j) acc[i][j] += wr[i] * er[j];
        }
        __syncthreads();
    }

#pragma unroll
    for (int i = 0; i < 8; ++i) {
        const int k = k0 + tk * 8 + i;
        const float bias = b0[k];
#pragma unroll
        for (int j = 0; j < 4; ++j) {
            const int b = tb * 4 + j;
            g_xg[((size_t)s * G3 + k) * BATCH + b] = acc[i][j] + bias;
        }
    }
}

// ---------------- layer-1 input projection: xg1[s][k][b] = y0[s,b,:] @ W1 + b1[0] ----
__global__ void __launch_bounds__(256) proj1_kernel(const float* __restrict__ W1,
                                                    const float* __restrict__ b1) {
    __shared__ float Ws[32][128];
    __shared__ float Es[32][65];

    const int t  = threadIdx.x;
    const int s  = blockIdx.y;
    const int k0 = blockIdx.x * 128;
    const int tk = t & 15;
    const int tb = t >> 4;

    float acc[8][4];
#pragma unroll
    for (int i = 0; i < 8; ++i)
#pragma unroll
        for (int j = 0; j < 4; ++j) acc[i][j] = 0.f;

    for (int it = 0; it < 16; ++it) {
        const int u0 = it * 32;
        for (int idx = t; idx < 32 * 128; idx += 256) {
            int r = idx >> 7, c = idx & 127;
            Ws[r][c] = W1[(size_t)(u0 + r) * G3 + k0 + c];
        }
        for (int idx = t; idx < 32 * BATCH; idx += 256) {
            int b = idx >> 5, u = idx & 31;
            Es[u][b] = g_y0[((size_t)s * BATCH + b) * UN + u0 + u];
        }
        __syncthreads();
#pragma unroll
        for (int d = 0; d < 32; ++d) {
            float wr[8], er[4];
#pragma unroll
            for (int i = 0; i < 8; ++i) wr[i] = Ws[d][tk * 8 + i];
#pragma unroll
            for (int j = 0; j < 4; ++j) er[j] = Es[d][tb * 4 + j];
#pragma unroll
            for (int i = 0; i < 8; ++i)
#pragma unroll
                for (int j = 0; j < 4; ++j) acc[i][j] += wr[i] * er[j];
        }
        __syncthreads();
    }

#pragma unroll
    for (int i = 0; i < 8; ++i) {
        const int k = k0 + tk * 8 + i;
        const float bias = b1[k];
#pragma unroll
        for (int j = 0; j < 4; ++j) {
            const int b = tb * 4 + j;
            g_xg[((size_t)s * G3 + k) * BATCH + b] = acc[i][j] + bias;
        }
    }
}

// ---------------- persistent GRU scan ----------------
// 128 CTAs x 256 threads. CTA owns 4 unit-columns; its U slice (512x12 f32) lives in
// SMEM for the whole scan. Warps split K 8-ways (64 each); partials reduced via SMEM.
// h double-buffer in global, broadcast via L2 (__ldcg/__stcg only — L1 is stale across
// the grid barrier). One grid barrier per step.
__global__ void __launch_bounds__(256) gru_scan(const float* __restrict__ Umat,
                                                const float* __restrict__ brec,
                                                int layer1, float* __restrict__ out) {
    extern __shared__ float sm[];
    float* u_s  = sm;             // [512][16] : [k][gate*4 + ci], 3 float4s per k
    float* part = sm + 512 * 16;  // [8 warps][768]

    const int t  = threadIdx.x;
    const int l  = t & 31;
    const int w  = t >> 5;
    const int c0 = blockIdx.x * 4;

    __shared__ unsigned s_genbase;
    if (t == 0) s_genbase = *(volatile unsigned*)&g_gen;

    // Load this CTA's U slice: columns {c0..c0+3} of each gate block.
    for (int idx = t; idx < 512 * 12; idx += 256) {
        int k = idx / 12, j = idx % 12;
        int g = j >> 2, ci = j & 3;
        u_s[k * 16 + j] = Umat[(size_t)k * G3 + g * UN + c0 + ci];
    }
    // Zero h buffer 0 (grid-strided).
    for (int idx = blockIdx.x * 256 + t; idx < UN * BATCH; idx += NCTA * 256)
        __stcg(&(&g_h[0][0][0])[idx], 0.f);
    __syncthreads();

    const unsigned genbase = s_genbase;
    unsigned nbar = 0;
    if (t == 0) grid_bar_impl(++nbar, genbase);
    __syncthreads();

    int p = 0;
    for (int s = 0; s < SEQ; ++s) {
        // ---- partial dot products: warp w covers k in [64w, 64w+64), lane l covers b=2l,2l+1
        float az[8], ar[8], ah[8];
#pragma unroll
        for (int i = 0; i < 8; ++i) { az[i] = 0.f; ar[i] = 0.f; ah[i] = 0.f; }

        const int kbase = w * 64;
        const float2* hrow = (const float2*)&g_h[p][kbase][2 * l];
#pragma unroll 4
        for (int kk = 0; kk < 64; ++kk) {
            const float2 h2 = __ldcg(hrow + (size_t)kk * (BATCH / 2));
            const float4* up = (const float4*)&u_s[(kbase + kk) * 16];
            const float4 uz = up[0];
            const float4 ur = up[1];
            const float4 uh = up[2];
            az[0] += h2.x * uz.x; az[1] += h2.x * uz.y; az[2] += h2.x * uz.z; az[3] += h2.x * uz.w;
            az[4] += h2.y * uz.x; az[5] += h2.y * uz.y; az[6] += h2.y * uz.z; az[7] += h2.y * uz.w;
            ar[0] += h2.x * ur.x; ar[1] += h2.x * ur.y; ar[2] += h2.x * ur.z; ar[3] += h2.x * ur.w;
            ar[4] += h2.y * ur.x; ar[5] += h2.y * ur.y; ar[6] += h2.y * ur.z; ar[7] += h2.y * ur.w;
            ah[0] += h2.x * uh.x; ah[1] += h2.x * uh.y; ah[2] += h2.x * uh.z; ah[3] += h2.x * uh.w;
            ah[4] += h2.y * uh.x; ah[5] += h2.y * uh.y; ah[6] += h2.y * uh.z; ah[7] += h2.y * uh.w;
        }

        float* pw = &part[w * 768];
        *(float4*)&pw[      8 * l    ] = make_float4(az[0], az[1], az[2], az[3]);
        *(float4*)&pw[      8 * l + 4] = make_float4(az[4], az[5], az[6], az[7]);
        *(float4*)&pw[256 + 8 * l    ] = make_float4(ar[0], ar[1], ar[2], ar[3]);
        *(float4*)&pw[256 + 8 * l + 4] = make_float4(ar[4], ar[5], ar[6], ar[7]);
        *(float4*)&pw[512 + 8 * l    ] = make_float4(ah[0], ah[1], ah[2], ah[3]);
        *(float4*)&pw[512 + 8 * l + 4] = make_float4(ah[4], ah[5], ah[6], ah[7]);
        __syncthreads();

        // ---- reduce 8 warp-partials, apply gates. thread t -> (b = t>>2, ci = t&3)
        {
            const int b  = t >> 2;
            const int ci = t & 3;
            const int c  = c0 + ci;
            float rz = 0.f, rr = 0.f, rh = 0.f;
#pragma unroll
            for (int ww = 0; ww < 8; ++ww) {
                const float* pp = &part[ww * 768 + t];
                rz += pp[0]; rr += pp[256]; rh += pp[512];
            }
            rz += brec[c];
            rr += brec[UN + c];
            rh += brec[2 * UN + c];

            const float* xgp = &g_xg[(size_t)s * G3 * BATCH];
            const float xz = __ldg(&xgp[(size_t)c * BATCH + b]);
            const float xr = __ldg(&xgp[(size_t)(UN + c) * BATCH + b]);
            const float xh = __ldg(&xgp[(size_t)(2 * UN + c) * BATCH + b]);

            const float z  = sigf(xz + rz);
            const float r  = sigf(xr + rr);
            const float hh = tanhf(xh + r * rh);
            const float hprev = __ldcg(&g_h[p][c][b]);
            const float hn = z * hprev + (1.f - z) * hh;
            __stcg(&g_h[p ^ 1][c][b], hn);

            if (!layer1) {
                g_y0[((size_t)s * BATCH + b) * UN + c] = hn;
            } else {
                out[((size_t)b * SEQ + s) * UN + c] = hn;
                if (s == SEQ - 1)
                    out[(size_t)BATCH * SEQ * UN + (size_t)b * UN + c] = hn;
            }
        }

        p ^= 1;
        __syncthreads();
        if (t == 0) grid_bar_impl(++nbar, genbase);
        __syncthreads();
    }
}

// ---------------- launch ----------------
extern "C" void kernel_launch(void* const* d_in, const int* in_sizes, int n_in,
                              void* d_out, int out_size) {
    const int*   tokens = (const int*)d_in[0];
    const float* emb    = (const float*)d_in[1];
    const float* W0     = (const float*)d_in[2];
    const float* U0     = (const float*)d_in[3];
    const float* b0     = (const float*)d_in[4];
    const float* W1     = (const float*)d_in[5];
    const float* U1     = (const float*)d_in[6];
    const float* b1     = (const float*)d_in[7];
    float* out = (float*)d_out;

    const size_t shmem = (512 * 16 + 8 * 768) * sizeof(float);  // 56 KB
    cudaFuncSetAttribute(gru_scan, cudaFuncAttributeMaxDynamicSharedMemorySize, (int)shmem);

    dim3 pgrid(12, 512);
    proj0_kernel<<<pgrid, 256>>>(tokens, emb, W0, b0);
    gru_scan<<<NCTA, 256, shmem>>>(U0, b0 + G3, 0, nullptr);
    proj1_kernel<<<pgrid, 256>>>(W1, b1);
    gru_scan<<<NCTA, 256, shmem>>>(U1, b1 + G3, 1, out);
}